// round 6
// baseline (speedup 1.0000x reference)
#include <cuda_runtime.h>
#include <cuda_bf16.h>
#include <math.h>

typedef unsigned long long ull;
typedef unsigned int u32;

// Problem constants
#define BATCH 2
#define TT 2048
#define DD 2048
#define HK 16
#define HV 32
#define KD 128
#define VD 128
#define KEY_DIM 2048
#define VALUE_DIM 4096
#define QKVZ_N 12288
#define BT (BATCH*TT)

// ---------------------------------------------------------------------------
// Scratch
// ---------------------------------------------------------------------------
__device__ float g_qkvz[(size_t)BT * QKVZ_N];        // 201 MB
__device__ float g_ba  [(size_t)BT * 64];
__device__ float g_qn  [(size_t)BT * HK * KD];
__device__ float g_kn  [(size_t)BT * HK * KD];
__device__ float g_v   [(size_t)BT * HV * VD];
__device__ float g_o   [(size_t)BT * HV * VD];
__device__ float g_x   [(size_t)BT * VALUE_DIM];
__device__ float g_g   [(size_t)BT * HV];
__device__ float g_beta[(size_t)BT * HV];
__device__ float g_atf [(size_t)BT * DD];            // hs tf32-rounded
__device__ float g_w1  [(size_t)QKVZ_N * DD];        // W_qkvz^T tf32 [N,K]
__device__ float g_w2  [(size_t)DD * VALUE_DIM];     // W_out^T tf32  [N,K]

// ---------------------------------------------------------------------------
// Helpers
// ---------------------------------------------------------------------------
__device__ __forceinline__ u32 f2tf(float x) {
    u32 r; asm("cvt.rna.tf32.f32 %0, %1;" : "=r"(r) : "f"(x));
    return r;
}
__device__ __forceinline__ float silu_f(float x) {
    return x / (1.f + __expf(-x));
}
__device__ __forceinline__ ull ffma2(ull a, ull b, ull c) {
    ull d; asm("fma.rn.f32x2 %0, %1, %2, %3;" : "=l"(d) : "l"(a), "l"(b), "l"(c));
    return d;
}
__device__ __forceinline__ ull fmul2(ull a, ull b) {
    ull d; asm("mul.rn.f32x2 %0, %1, %2;" : "=l"(d) : "l"(a), "l"(b));
    return d;
}
__device__ __forceinline__ ull pack2(float x, float y) {
    ull r; asm("mov.b64 %0, {%1, %2};" : "=l"(r) : "f"(x), "f"(y));
    return r;
}
__device__ __forceinline__ float lo2(ull a) { return __uint_as_float((u32)(a & 0xffffffffull)); }
__device__ __forceinline__ float hi2(ull a) { return __uint_as_float((u32)(a >> 32)); }

__device__ __forceinline__ u32 cvta_smem(const void* p) {
    u32 a;
    asm("{ .reg .u64 t; cvta.to.shared.u64 t, %1; cvt.u32.u64 %0, t; }"
        : "=r"(a) : "l"(p));
    return a;
}
__device__ __forceinline__ void cp16(u32 dst, const void* src) {
    asm volatile("cp.async.cg.shared.global [%0], [%1], 16;"
                 :: "r"(dst), "l"(src) : "memory");
}
__device__ __forceinline__ void ldsm4(u32& r0, u32& r1, u32& r2, u32& r3, u32 a) {
    asm volatile("ldmatrix.sync.aligned.m8n8.x4.shared.b16 {%0,%1,%2,%3}, [%4];"
                 : "=r"(r0), "=r"(r1), "=r"(r2), "=r"(r3) : "r"(a));
}

// ---------------------------------------------------------------------------
// tf32 mma.sync GEMM v2: C[M,N] = A[M,K] * Bt[N,K]^T (both tf32-pre-rounded,
// row-major fp32 storage). Tile 128x128x32, 4 warps, 64x64 warp tiles,
// ldmatrix fragment loads, 3-stage cp.async, 2 CTAs/SM.
// Smem rows padded to 36 floats (144B) => conflict-free LDSM.
// ---------------------------------------------------------------------------
#define AROWF 36
#define STAGE_BYTES (2*128*AROWF*4)       // A + B = 36864
#define NSTAGES 3
#define GEMM_SMEM (NSTAGES*STAGE_BYTES)   // 110592

__device__ __forceinline__ void gemm_load_stage(
    u32 sb, const float* __restrict__ Ag, const float* __restrict__ Bg,
    int K, int kiter, int buf, int tid)
{
    const u32 st = sb + (u32)buf * STAGE_BYTES;
    const int k0 = kiter * 32;
#pragma unroll
    for (int j = 0; j < 8; j++) {          // A: 128 rows x 8 chunks
        int c = tid + j * 128;
        int r = c >> 3, cc = c & 7;
        cp16(st + (u32)(r * 144 + cc * 16), Ag + (size_t)r * K + k0 + cc * 4);
    }
#pragma unroll
    for (int j = 0; j < 8; j++) {          // B: 128 n-rows x 8 chunks
        int c = tid + j * 128;
        int r = c >> 3, cc = c & 7;
        cp16(st + (u32)(128 * 144 + r * 144 + cc * 16),
             Bg + (size_t)r * K + k0 + cc * 4);
    }
}

__global__ __launch_bounds__(128, 2) void tf32_gemm_kernel(
    const float* __restrict__ A, const float* __restrict__ Bt,
    float* __restrict__ C, int M, int N, int K)
{
    extern __shared__ __align__(16) float smem[];
    const u32 sb = cvta_smem(smem);
    const int tid = threadIdx.x;
    const int bx = blockIdx.x;     // N tile
    const int by = blockIdx.y;     // M tile
    const int warp = tid >> 5;
    const int lane = tid & 31;
    const int g = lane >> 2;
    const int tg = lane & 3;
    const int warp_m = warp >> 1;  // 0..1
    const int warp_n = warp & 1;   // 0..1
    const int niters = K >> 5;

    // ldmatrix lane->address bases
    // A: lanes 0-7 rows 0-7 chunk0 | 8-15 rows 8-15 chunk0 | 16-23 rows 0-7
    //    chunk1(+4 floats) | 24-31 rows 8-15 chunk1   => frags a0..a3
    const u32 a_base = sb +
        (u32)(((warp_m * 64 + (lane & 15)) * AROWF + ((lane >> 4) << 2)) * 4);
    // B (n-major): rows = n, cols = k. x4 covers nt pair.
    const u32 b_base = sb + 128 * 144 +
        (u32)(((warp_n * 64 + (lane & 7) + ((lane & 16) >> 1)) * AROWF
               + ((lane & 8) >> 1)) * 4);

    const float* Ag = A + (size_t)(by * 128) * K;
    const float* Bg = Bt + (size_t)(bx * 128) * K;

    float acc[4][8][4];
#pragma unroll
    for (int mt = 0; mt < 4; mt++)
#pragma unroll
        for (int nt = 0; nt < 8; nt++)
#pragma unroll
            for (int r = 0; r < 4; r++) acc[mt][nt][r] = 0.f;

    // prologue: stages 0,1
#pragma unroll
    for (int s = 0; s < NSTAGES - 1; s++) {
        gemm_load_stage(sb, Ag, Bg, K, s, s, tid);
        asm volatile("cp.async.commit_group;" ::: "memory");
    }

    int buf = 0;
    for (int i = 0; i < niters; i++) {
        asm volatile("cp.async.wait_group %0;" :: "n"(NSTAGES - 2) : "memory");
        __syncthreads();

        // issue next stage loads first (into the buffer consumed 2 iters ago)
        if (i + NSTAGES - 1 < niters) {
            int nb = buf + NSTAGES - 1; if (nb >= NSTAGES) nb -= NSTAGES;
            gemm_load_stage(sb, Ag, Bg, K, i + NSTAGES - 1, nb, tid);
        }
        asm volatile("cp.async.commit_group;" ::: "memory");

        const u32 ab = a_base + (u32)buf * STAGE_BYTES;
        const u32 bb = b_base + (u32)buf * STAGE_BYTES;
#pragma unroll
        for (int ks = 0; ks < 4; ks++) {
            u32 af[4][4];
#pragma unroll
            for (int mt = 0; mt < 4; mt++)
                ldsm4(af[mt][0], af[mt][1], af[mt][2], af[mt][3],
                      ab + (u32)((mt * 16 * AROWF + ks * 8) * 4));
            u32 bf[8][2];
#pragma unroll
            for (int p = 0; p < 4; p++) {
                u32 t0, t1, t2, t3;
                ldsm4(t0, t1, t2, t3,
                      bb + (u32)((p * 16 * AROWF + ks * 8) * 4));
                bf[2 * p][0] = t0; bf[2 * p][1] = t1;
                bf[2 * p + 1][0] = t2; bf[2 * p + 1][1] = t3;
            }
#pragma unroll
            for (int mt = 0; mt < 4; mt++)
#pragma unroll
                for (int nt = 0; nt < 8; nt++) {
                    asm volatile(
                        "mma.sync.aligned.m16n8k8.row.col.f32.tf32.tf32.f32 "
                        "{%0,%1,%2,%3}, {%4,%5,%6,%7}, {%8,%9}, {%0,%1,%2,%3};\n"
                        : "+f"(acc[mt][nt][0]), "+f"(acc[mt][nt][1]),
                          "+f"(acc[mt][nt][2]), "+f"(acc[mt][nt][3])
                        : "r"(af[mt][0]), "r"(af[mt][1]),
                          "r"(af[mt][2]), "r"(af[mt][3]),
                          "r"(bf[nt][0]), "r"(bf[nt][1]));
                }
        }
        buf++; if (buf >= NSTAGES) buf = 0;
    }

    // epilogue
#pragma unroll
    for (int mt = 0; mt < 4; mt++) {
        int row = by * 128 + warp_m * 64 + mt * 16 + g;
#pragma unroll
        for (int nt = 0; nt < 8; nt++) {
            int col = bx * 128 + warp_n * 64 + nt * 8 + tg * 2;
            *(float2*)(C + (size_t)row * N + col) =
                make_float2(acc[mt][nt][0], acc[mt][nt][1]);
            *(float2*)(C + (size_t)(row + 8) * N + col) =
                make_float2(acc[mt][nt][2], acc[mt][nt][3]);
        }
    }
}

// ---------------------------------------------------------------------------
// Prep: elementwise tf32 round
// ---------------------------------------------------------------------------
__global__ __launch_bounds__(256) void convert_tf32_kernel(
    const float* __restrict__ in, float* __restrict__ out, int n4)
{
    int i = blockIdx.x * 256 + threadIdx.x;
    if (i < n4) {
        float4 v = ((const float4*)in)[i];
        v.x = __uint_as_float(f2tf(v.x));
        v.y = __uint_as_float(f2tf(v.y));
        v.z = __uint_as_float(f2tf(v.z));
        v.w = __uint_as_float(f2tf(v.w));
        ((float4*)out)[i] = v;
    }
}

// ---------------------------------------------------------------------------
// Prep: transpose + tf32 round. src [R,C] -> dst [C,R]
// ---------------------------------------------------------------------------
__global__ __launch_bounds__(256) void transpose_tf32_kernel(
    const float* __restrict__ src, float* __restrict__ dst, int R, int C)
{
    __shared__ float t[32][33];
    const int bx = blockIdx.x * 32;  // C offset
    const int by = blockIdx.y * 32;  // R offset
    const int tx = threadIdx.x & 31;
    const int ty = threadIdx.x >> 5;
#pragma unroll
    for (int j = 0; j < 32; j += 8)
        t[ty + j][tx] = src[(size_t)(by + ty + j) * C + bx + tx];
    __syncthreads();
#pragma unroll
    for (int j = 0; j < 32; j += 8)
        dst[(size_t)(bx + ty + j) * R + by + tx] =
            __uint_as_float(f2tf(t[tx][ty + j]));
}

// ---------------------------------------------------------------------------
// ba = hs @ W_ba : 4-way k-split
// ---------------------------------------------------------------------------
__global__ __launch_bounds__(256) void ba_kernel(
    const float* __restrict__ hs, const float* __restrict__ Wba,
    float* __restrict__ ba)
{
    __shared__ float hrow[DD];
    __shared__ float part[4][64];
    const int row = blockIdx.x;
    const int tid = threadIdx.x;
    for (int i = tid; i < DD; i += 256)
        hrow[i] = hs[(size_t)row * DD + i];
    __syncthreads();
    const int col = tid & 63;
    const int ks = tid >> 6;
    float acc = 0.f;
    const float* wb = Wba + (size_t)(ks * 512) * 64 + col;
    const float* hr = hrow + ks * 512;
#pragma unroll 8
    for (int j = 0; j < 512; j++)
        acc += hr[j] * wb[(size_t)j * 64];
    part[ks][col] = acc;
    __syncthreads();
    if (tid < 64)
        ba[(size_t)row * 64 + tid] =
            part[0][tid] + part[1][tid] + part[2][tid] + part[3][tid];
}

// ---------------------------------------------------------------------------
// conv + silu + l2norm + gating
// ---------------------------------------------------------------------------
__global__ __launch_bounds__(256) void conv_gate_kernel(
    const float* __restrict__ qkvz, const float* __restrict__ ba,
    const float* __restrict__ convw, const float* __restrict__ Alog,
    const float* __restrict__ dtb,
    float* __restrict__ qn, float* __restrict__ kn, float* __restrict__ vv,
    float* __restrict__ gg, float* __restrict__ bb)
{
    const int bt = blockIdx.x;
    const int b = bt / TT;
    const int t = bt % TT;
    const int tid = threadIdx.x;
    __shared__ float buf[2 * KEY_DIM];
    __shared__ float rnorm[2 * HK];

    for (int c = tid; c < 2 * KEY_DIM; c += 256) {
        float acc = 0.f;
#pragma unroll
        for (int j = 0; j < 4; j++) {
            int ts = t - 3 + j;
            if (ts >= 0)
                acc += convw[c * 4 + j] * qkvz[((size_t)b * TT + ts) * QKVZ_N + c];
        }
        buf[c] = silu_f(acc);
    }
    __syncthreads();

    const int warp = tid >> 5;
    const int lane = tid & 31;
    for (int gi = warp; gi < 32; gi += 8) {
        float s = 0.f;
#pragma unroll
        for (int l = 0; l < 4; l++) {
            float x = buf[gi * 128 + lane + 32 * l];
            s += x * x;
        }
#pragma unroll
        for (int off = 16; off; off >>= 1)
            s += __shfl_xor_sync(0xffffffffu, s, off);
        if (lane == 0) rnorm[gi] = rsqrtf(s + 1e-6f);
    }
    __syncthreads();

    const float QSCALE = 0.08838834764831845f;
    for (int i = tid; i < KEY_DIM; i += 256) {
        int kh = i >> 7;
        int d  = i & 127;
        size_t o0 = ((size_t)bt * HK + kh) * KD + d;
        qn[o0] = buf[i] * rnorm[kh] * QSCALE;
        kn[o0] = buf[KEY_DIM + i] * rnorm[HK + kh];
    }

    for (int c = tid; c < VALUE_DIM; c += 256) {
        int cc = 2 * KEY_DIM + c;
        float acc = 0.f;
#pragma unroll
        for (int j = 0; j < 4; j++) {
            int ts = t - 3 + j;
            if (ts >= 0)
                acc += convw[cc * 4 + j] * qkvz[((size_t)b * TT + ts) * QKVZ_N + cc];
        }
        vv[(size_t)bt * VALUE_DIM + c] = silu_f(acc);
    }

    if (tid < HV) {
        float bg = ba[(size_t)bt * 64 + tid];
        float a  = ba[(size_t)bt * 64 + 32 + tid] + dtb[tid];
        bb[(size_t)bt * HV + tid] = 1.f / (1.f + __expf(-bg));
        float sp = (a > 20.f) ? a : log1pf(__expf(a));
        gg[(size_t)bt * HV + tid] = -__expf(Alog[tid]) * sp;
    }
}

// ---------------------------------------------------------------------------
// Gated delta-rule scan (split dependency chains; exp(g) in prefetch)
// ---------------------------------------------------------------------------
struct ScanBuf {
    ulonglong2 k[8];
    ulonglong2 q[8];
    float v, eg, beta;
};

__device__ __forceinline__ void scan_load(
    ScanBuf& sb, int t, int b, int kh, int h, int kq, int vcol,
    const float* __restrict__ qn, const float* __restrict__ kn,
    const float* __restrict__ vv, const float* __restrict__ gg,
    const float* __restrict__ bb)
{
    int tc = t < TT ? t : TT - 1;
    size_t ik = (((size_t)b * TT + tc) * HK + kh) * (size_t)KD + kq * 32;
    size_t iv = (((size_t)b * TT + tc) * HV + h) * (size_t)VD + vcol;
    const ulonglong2* kp = (const ulonglong2*)(kn + ik);
    const ulonglong2* qp = (const ulonglong2*)(qn + ik);
#pragma unroll
    for (int i = 0; i < 8; i++) { sb.k[i] = kp[i]; sb.q[i] = qp[i]; }
    sb.v = vv[iv];
    size_t ig = ((size_t)b * TT + tc) * HV + h;
    sb.eg = __expf(gg[ig]);
    sb.beta = bb[ig];
}

__device__ __forceinline__ void scan_step(
    ull* __restrict__ S2, const ScanBuf& sb, int t, int b, int h, int kq,
    int vcol, float* __restrict__ oo)
{
    ull eg2 = pack2(sb.eg, sb.eg);
    ull p2a = 0ull, p2b = 0ull;
#pragma unroll
    for (int i = 0; i < 8; i++) {
        S2[2*i]   = fmul2(S2[2*i],   eg2);
        p2a = ffma2(sb.k[i].x, S2[2*i],   p2a);
        S2[2*i+1] = fmul2(S2[2*i+1], eg2);
        p2b = ffma2(sb.k[i].y, S2[2*i+1], p2b);
    }
    float p = (lo2(p2a) + hi2(p2a)) + (lo2(p2b) + hi2(p2b));
    p += __shfl_xor_sync(0xffffffffu, p, 1);
    p += __shfl_xor_sync(0xffffffffu, p, 2);
    float delta = (sb.v - p) * sb.beta;
    ull d2 = pack2(delta, delta);
    ull o2a = 0ull, o2b = 0ull;
#pragma unroll
    for (int i = 0; i < 8; i++) {
        S2[2*i]   = ffma2(sb.k[i].x, d2, S2[2*i]);
        o2a = ffma2(sb.q[i].x, S2[2*i],   o2a);
        S2[2*i+1] = ffma2(sb.k[i].y, d2, S2[2*i+1]);
        o2b = ffma2(sb.q[i].y, S2[2*i+1], o2b);
    }
    float o = (lo2(o2a) + hi2(o2a)) + (lo2(o2b) + hi2(o2b));
    o += __shfl_xor_sync(0xffffffffu, o, 1);
    o += __shfl_xor_sync(0xffffffffu, o, 2);
    if (kq == 0) {
        size_t iv = (((size_t)b * TT + t) * HV + h) * (size_t)VD + vcol;
        oo[iv] = o;
    }
}

__global__ __launch_bounds__(256, 1) void scan_kernel(
    const float* __restrict__ qn, const float* __restrict__ kn,
    const float* __restrict__ vv, const float* __restrict__ gg,
    const float* __restrict__ bb, float* __restrict__ oo)
{
    const int bh2 = blockIdx.x;
    const int b = bh2 >> 6;
    const int rem = bh2 & 63;
    const int h = rem >> 1;
    const int vhalf = rem & 1;
    const int tid = threadIdx.x;
    const int colL = tid >> 2;
    const int kq = tid & 3;
    const int vcol = vhalf * 64 + colL;
    const int kh = h >> 1;

    ull S2[16];
#pragma unroll
    for (int i = 0; i < 16; i++) S2[i] = 0ull;

    ScanBuf bA, bB;
    scan_load(bA, 0, b, kh, h, kq, vcol, qn, kn, vv, gg, bb);

    for (int t = 0; t < TT; t += 2) {
        scan_load(bB, t + 1, b, kh, h, kq, vcol, qn, kn, vv, gg, bb);
        scan_step(S2, bA, t, b, h, kq, vcol, oo);
        scan_load(bA, t + 2, b, kh, h, kq, vcol, qn, kn, vv, gg, bb);
        scan_step(S2, bB, t + 1, b, h, kq, vcol, oo);
    }
}

// ---------------------------------------------------------------------------
// gated rmsnorm (stores tf32-rounded x for GEMM2's A operand)
// ---------------------------------------------------------------------------
__global__ __launch_bounds__(256) void rmsnorm_kernel(
    const float* __restrict__ oo, const float* __restrict__ qkvz,
    const float* __restrict__ nw, float* __restrict__ xout)
{
    const int bt = blockIdx.x;
    const int warp = threadIdx.x >> 5;
    const int lane = threadIdx.x & 31;

    for (int hh = warp; hh < HV; hh += 8) {
        const size_t base = ((size_t)bt * HV + hh) * (size_t)VD;
        const float* zz = qkvz + (size_t)bt * QKVZ_N + 2 * KEY_DIM + VALUE_DIM
                          + (size_t)hh * VD;
        float xv[4];
        float ss = 0.f;
#pragma unroll
        for (int i = 0; i < 4; i++) {
            int d = lane + 32 * i;
            float z = zz[d];
            float x = oo[base + d] * silu_f(z);
            xv[i] = x;
            ss += x * x;
        }
#pragma unroll
        for (int off = 16; off; off >>= 1)
            ss += __shfl_xor_sync(0xffffffffu, ss, off);
        float r = rsqrtf(ss * (1.f / 128.f) + 1e-6f);
#pragma unroll
        for (int i = 0; i < 4; i++) {
            int d = lane + 32 * i;
            xout[(size_t)bt * VALUE_DIM + hh * VD + d] =
                __uint_as_float(f2tf(xv[i] * r * (1.f + nw[d])));
        }
    }
}

// ---------------------------------------------------------------------------
// Launch
// ---------------------------------------------------------------------------
extern "C" void kernel_launch(void* const* d_in, const int* in_sizes, int n_in,
                              void* d_out, int out_size)
{
    const float* hs    = (const float*)d_in[0];
    const float* Wqkvz = (const float*)d_in[1];
    const float* Wba   = (const float*)d_in[2];
    const float* convw = (const float*)d_in[3];
    const float* Alog  = (const float*)d_in[4];
    const float* dtb   = (const float*)d_in[5];
    const float* nw    = (const float*)d_in[6];
    const float* Wout  = (const float*)d_in[7];
    float* out = (float*)d_out;

    float *qkvz, *ba, *qn, *kn, *vv, *oo, *xx, *gg, *bb, *atf, *w1, *w2;
    cudaGetSymbolAddress((void**)&qkvz, g_qkvz);
    cudaGetSymbolAddress((void**)&ba,   g_ba);
    cudaGetSymbolAddress((void**)&qn,   g_qn);
    cudaGetSymbolAddress((void**)&kn,   g_kn);
    cudaGetSymbolAddress((void**)&vv,   g_v);
    cudaGetSymbolAddress((void**)&oo,   g_o);
    cudaGetSymbolAddress((void**)&xx,   g_x);
    cudaGetSymbolAddress((void**)&gg,   g_g);
    cudaGetSymbolAddress((void**)&bb,   g_beta);
    cudaGetSymbolAddress((void**)&atf,  g_atf);
    cudaGetSymbolAddress((void**)&w1,   g_w1);
    cudaGetSymbolAddress((void**)&w2,   g_w2);

    cudaFuncSetAttribute(tf32_gemm_kernel,
                         cudaFuncAttributeMaxDynamicSharedMemorySize, GEMM_SMEM);

    // prep: round A to tf32; transpose+round weights into [N,K]
    convert_tf32_kernel<<<(BT * DD / 4 + 255) / 256, 256>>>(hs, atf, BT * DD / 4);
    transpose_tf32_kernel<<<dim3(QKVZ_N / 32, DD / 32), 256>>>(Wqkvz, w1, DD, QKVZ_N);
    transpose_tf32_kernel<<<dim3(DD / 32, VALUE_DIM / 32), 256>>>(Wout, w2, VALUE_DIM, DD);

    // 1) qkvz = hs @ W_qkvz : [4096,2048]x[2048,12288]
    tf32_gemm_kernel<<<dim3(QKVZ_N / 128, BT / 128), 128, GEMM_SMEM>>>(
        atf, w1, qkvz, BT, QKVZ_N, DD);

    // 2) ba = hs @ W_ba
    ba_kernel<<<BT, 256>>>(hs, Wba, ba);

    // 3) conv + silu + l2norm + gating
    conv_gate_kernel<<<BT, 256>>>(qkvz, ba, convw, Alog, dtb, qn, kn, vv, gg, bb);

    // 4) gated delta rule scan
    scan_kernel<<<128, 256>>>(qn, kn, vv, gg, bb, oo);

    // 5) gated rmsnorm
    rmsnorm_kernel<<<BT, 256>>>(oo, qkvz, nw, xx);

    // 6) out = x @ W_out : [4096,4096]x[4096,2048]
    tf32_gemm_kernel<<<dim3(DD / 128, BT / 128), 128, GEMM_SMEM>>>(
        xx, w2, out, BT, DD, VALUE_DIM);
}

// round 7
// speedup vs baseline: 1.1925x; 1.1925x over previous
#include <cuda_runtime.h>
#include <cuda_fp16.h>
#include <math.h>

typedef unsigned long long ull;
typedef unsigned int u32;

// Problem constants
#define BATCH 2
#define TT 2048
#define DD 2048
#define HK 16
#define HV 32
#define KD 128
#define VD 128
#define KEY_DIM 2048
#define VALUE_DIM 4096
#define QKVZ_N 12288
#define BT (BATCH*TT)

// ---------------------------------------------------------------------------
// Scratch
// ---------------------------------------------------------------------------
__device__ float g_qkvz[(size_t)BT * QKVZ_N];        // 201 MB
__device__ float g_ba  [(size_t)BT * 64];
__device__ float g_qn  [(size_t)BT * HK * KD];
__device__ float g_kn  [(size_t)BT * HK * KD];
__device__ float g_v   [(size_t)BT * HV * VD];
__device__ float g_o   [(size_t)BT * HV * VD];
__device__ float g_g   [(size_t)BT * HV];
__device__ float g_beta[(size_t)BT * HV];
__device__ __half g_ah [(size_t)BT * DD];            // hs  fp16      [M,K]
__device__ __half g_w1h[(size_t)QKVZ_N * DD];        // W_qkvz^T fp16 [N,K]
__device__ __half g_w2h[(size_t)DD * VALUE_DIM];     // W_out^T fp16  [N,K]
__device__ __half g_xh [(size_t)BT * VALUE_DIM];     // rmsnorm out   [M,K]

// ---------------------------------------------------------------------------
// Helpers
// ---------------------------------------------------------------------------
__device__ __forceinline__ float silu_f(float x) {
    return x / (1.f + __expf(-x));
}
__device__ __forceinline__ ull ffma2(ull a, ull b, ull c) {
    ull d; asm("fma.rn.f32x2 %0, %1, %2, %3;" : "=l"(d) : "l"(a), "l"(b), "l"(c));
    return d;
}
__device__ __forceinline__ ull fmul2(ull a, ull b) {
    ull d; asm("mul.rn.f32x2 %0, %1, %2;" : "=l"(d) : "l"(a), "l"(b));
    return d;
}
__device__ __forceinline__ ull pack2(float x, float y) {
    ull r; asm("mov.b64 %0, {%1, %2};" : "=l"(r) : "f"(x), "f"(y));
    return r;
}
__device__ __forceinline__ float lo2(ull a) { return __uint_as_float((u32)(a & 0xffffffffull)); }
__device__ __forceinline__ float hi2(ull a) { return __uint_as_float((u32)(a >> 32)); }

__device__ __forceinline__ u32 cvta_smem(const void* p) {
    u32 a;
    asm("{ .reg .u64 t; cvta.to.shared.u64 t, %1; cvt.u32.u64 %0, t; }"
        : "=r"(a) : "l"(p));
    return a;
}
__device__ __forceinline__ void cp16(u32 dst, const void* src) {
    asm volatile("cp.async.cg.shared.global [%0], [%1], 16;"
                 :: "r"(dst), "l"(src) : "memory");
}
__device__ __forceinline__ void ldsm4(u32& r0, u32& r1, u32& r2, u32& r3, u32 a) {
    asm volatile("ldmatrix.sync.aligned.m8n8.x4.shared.b16 {%0,%1,%2,%3}, [%4];"
                 : "=r"(r0), "=r"(r1), "=r"(r2), "=r"(r3) : "r"(a));
}

// ---------------------------------------------------------------------------
// fp16 mma.sync GEMM: C[M,N](f32) = A[M,K](f16) * Bt[N,K](f16)^T.
// Tile 128x128x32, 256 threads (8 warps), warp tile 32x64, m16n8k16 mma,
// ldmatrix fragments, 4-stage cp.async, 2 CTAs/SM.
// Smem rows: 32 data halves + 8 pad = 40 halves (80 B) -> conflict-free LDSM.
// ---------------------------------------------------------------------------
#define ROWB 80
#define SB_OFF (128*ROWB)                  // 10240
#define STAGE_BYTES (2*128*ROWB)           // 20480
#define NSTAGES 4
#define GEMM_SMEM (NSTAGES*STAGE_BYTES)    // 81920

__device__ __forceinline__ void gemm_load_stage(
    u32 sb, const __half* __restrict__ Ag, const __half* __restrict__ Bg,
    int K, int kiter, int buf, int tid)
{
    const u32 st = sb + (u32)buf * STAGE_BYTES;
    const int k0 = kiter * 32;
#pragma unroll
    for (int j = 0; j < 2; j++) {          // A: 128 rows x 4 chunks(8 halves)
        int c = tid + j * 256;
        int r = c >> 2, cc = c & 3;
        cp16(st + (u32)(r * ROWB + cc * 16), Ag + (size_t)r * K + k0 + cc * 8);
    }
#pragma unroll
    for (int j = 0; j < 2; j++) {          // B: 128 n-rows x 4 chunks
        int c = tid + j * 256;
        int r = c >> 2, cc = c & 3;
        cp16(st + (u32)(SB_OFF + r * ROWB + cc * 16),
             Bg + (size_t)r * K + k0 + cc * 8);
    }
}

__global__ __launch_bounds__(256, 2) void h_gemm_kernel(
    const __half* __restrict__ A, const __half* __restrict__ Bt,
    float* __restrict__ C, int M, int N, int K)
{
    extern __shared__ __align__(16) char smem[];
    const u32 sb = cvta_smem(smem);
    const int tid = threadIdx.x;
    const int bx = blockIdx.x;     // N tile
    const int by = blockIdx.y;     // M tile
    const int warp = tid >> 5;
    const int lane = tid & 31;
    const int g = lane >> 2;
    const int tg = lane & 3;
    const int warp_m = warp >> 1;  // 0..3 -> 32 rows
    const int warp_n = warp & 1;   // 0..1 -> 64 cols
    const int niters = K >> 5;

    // ldmatrix bases: lanes 0-15 -> 16 rows at k-chunk 0 (matrices 0,1);
    // lanes 16-31 -> same rows at +16 B (k halves 8-15; matrices 2,3)
    const u32 a_base = sb +
        (u32)((warp_m * 32 + (lane & 15)) * ROWB + ((lane >> 4) << 4));
    const u32 b_base = sb + SB_OFF +
        (u32)((warp_n * 64 + (lane & 15)) * ROWB + ((lane >> 4) << 4));

    const __half* Ag = A + (size_t)(by * 128) * K;
    const __half* Bg = Bt + (size_t)(bx * 128) * K;

    float acc[2][8][4];
#pragma unroll
    for (int mt = 0; mt < 2; mt++)
#pragma unroll
        for (int nt = 0; nt < 8; nt++)
#pragma unroll
            for (int r = 0; r < 4; r++) acc[mt][nt][r] = 0.f;

    // prologue
#pragma unroll
    for (int s = 0; s < NSTAGES - 1; s++) {
        gemm_load_stage(sb, Ag, Bg, K, s, s, tid);
        asm volatile("cp.async.commit_group;" ::: "memory");
    }

    int buf = 0;
    for (int i = 0; i < niters; i++) {
        asm volatile("cp.async.wait_group %0;" :: "n"(NSTAGES - 2) : "memory");
        __syncthreads();

        if (i + NSTAGES - 1 < niters) {
            int nb = buf + NSTAGES - 1; if (nb >= NSTAGES) nb -= NSTAGES;
            gemm_load_stage(sb, Ag, Bg, K, i + NSTAGES - 1, nb, tid);
        }
        asm volatile("cp.async.commit_group;" ::: "memory");

        const u32 ab = a_base + (u32)buf * STAGE_BYTES;
        const u32 bb = b_base + (u32)buf * STAGE_BYTES;
#pragma unroll
        for (int ks = 0; ks < 2; ks++) {   // two k16 chunks per 32-k stage
            u32 af[2][4];
#pragma unroll
            for (int mt = 0; mt < 2; mt++)
                ldsm4(af[mt][0], af[mt][1], af[mt][2], af[mt][3],
                      ab + (u32)(mt * 16 * ROWB + ks * 32));
            u32 bf[8][2];
#pragma unroll
            for (int p = 0; p < 4; p++) {
                u32 m0, m1, m2, m3;
                ldsm4(m0, m1, m2, m3, bb + (u32)(p * 16 * ROWB + ks * 32));
                bf[2 * p][0] = m0;     bf[2 * p][1] = m2;
                bf[2 * p + 1][0] = m1; bf[2 * p + 1][1] = m3;
            }
#pragma unroll
            for (int mt = 0; mt < 2; mt++)
#pragma unroll
                for (int nt = 0; nt < 8; nt++) {
                    asm volatile(
                        "mma.sync.aligned.m16n8k16.row.col.f32.f16.f16.f32 "
                        "{%0,%1,%2,%3}, {%4,%5,%6,%7}, {%8,%9}, {%0,%1,%2,%3};\n"
                        : "+f"(acc[mt][nt][0]), "+f"(acc[mt][nt][1]),
                          "+f"(acc[mt][nt][2]), "+f"(acc[mt][nt][3])
                        : "r"(af[mt][0]), "r"(af[mt][1]),
                          "r"(af[mt][2]), "r"(af[mt][3]),
                          "r"(bf[nt][0]), "r"(bf[nt][1]));
                }
        }
        buf++; if (buf >= NSTAGES) buf = 0;
    }

    // epilogue
#pragma unroll
    for (int mt = 0; mt < 2; mt++) {
        int row = by * 128 + warp_m * 32 + mt * 16 + g;
#pragma unroll
        for (int nt = 0; nt < 8; nt++) {
            int col = bx * 128 + warp_n * 64 + nt * 8 + tg * 2;
            *(float2*)(C + (size_t)row * N + col) =
                make_float2(acc[mt][nt][0], acc[mt][nt][1]);
            *(float2*)(C + (size_t)(row + 8) * N + col) =
                make_float2(acc[mt][nt][2], acc[mt][nt][3]);
        }
    }
}

// ---------------------------------------------------------------------------
// Prep: elementwise f32 -> f16
// ---------------------------------------------------------------------------
__global__ __launch_bounds__(256) void convert_h_kernel(
    const float* __restrict__ in, __half* __restrict__ out, int n4)
{
    int i = blockIdx.x * 256 + threadIdx.x;
    if (i < n4) {
        float4 v = ((const float4*)in)[i];
        __half2 h0 = __floats2half2_rn(v.x, v.y);
        __half2 h1 = __floats2half2_rn(v.z, v.w);
        ((__half2*)out)[2 * i] = h0;
        ((__half2*)out)[2 * i + 1] = h1;
    }
}

// ---------------------------------------------------------------------------
// Prep: transpose + f16 round. src [R,C] f32 -> dst [C,R] f16
// ---------------------------------------------------------------------------
__global__ __launch_bounds__(256) void transpose_h_kernel(
    const float* __restrict__ src, __half* __restrict__ dst, int R, int C)
{
    __shared__ float t[32][33];
    const int bx = blockIdx.x * 32;  // C offset
    const int by = blockIdx.y * 32;  // R offset
    const int tx = threadIdx.x & 31;
    const int ty = threadIdx.x >> 5;
#pragma unroll
    for (int j = 0; j < 32; j += 8)
        t[ty + j][tx] = src[(size_t)(by + ty + j) * C + bx + tx];
    __syncthreads();
#pragma unroll
    for (int j = 0; j < 32; j += 8)
        dst[(size_t)(bx + ty + j) * R + by + tx] = __float2half(t[tx][ty + j]);
}

// ---------------------------------------------------------------------------
// ba = hs @ W_ba : 4-way k-split
// ---------------------------------------------------------------------------
__global__ __launch_bounds__(256) void ba_kernel(
    const float* __restrict__ hs, const float* __restrict__ Wba,
    float* __restrict__ ba)
{
    __shared__ float hrow[DD];
    __shared__ float part[4][64];
    const int row = blockIdx.x;
    const int tid = threadIdx.x;
    for (int i = tid; i < DD; i += 256)
        hrow[i] = hs[(size_t)row * DD + i];
    __syncthreads();
    const int col = tid & 63;
    const int ks = tid >> 6;
    float acc = 0.f;
    const float* wb = Wba + (size_t)(ks * 512) * 64 + col;
    const float* hr = hrow + ks * 512;
#pragma unroll 8
    for (int j = 0; j < 512; j++)
        acc += hr[j] * wb[(size_t)j * 64];
    part[ks][col] = acc;
    __syncthreads();
    if (tid < 64)
        ba[(size_t)row * 64 + tid] =
            part[0][tid] + part[1][tid] + part[2][tid] + part[3][tid];
}

// ---------------------------------------------------------------------------
// conv + silu + l2norm + gating. v stored to g_v (via vv).
// ---------------------------------------------------------------------------
__global__ __launch_bounds__(256) void conv_gate_kernel(
    const float* __restrict__ qkvz, const float* __restrict__ ba,
    const float* __restrict__ convw, const float* __restrict__ Alog,
    const float* __restrict__ dtb,
    float* __restrict__ qn, float* __restrict__ kn, float* __restrict__ vv,
    float* __restrict__ gg, float* __restrict__ bb)
{
    const int bt = blockIdx.x;
    const int b = bt / TT;
    const int t = bt % TT;
    const int tid = threadIdx.x;
    __shared__ float buf[2 * KEY_DIM];
    __shared__ float rnorm[2 * HK];

    for (int c = tid; c < 2 * KEY_DIM; c += 256) {
        float acc = 0.f;
#pragma unroll
        for (int j = 0; j < 4; j++) {
            int ts = t - 3 + j;
            if (ts >= 0)
                acc += convw[c * 4 + j] * qkvz[((size_t)b * TT + ts) * QKVZ_N + c];
        }
        buf[c] = silu_f(acc);
    }
    __syncthreads();

    const int warp = tid >> 5;
    const int lane = tid & 31;
    for (int gi = warp; gi < 32; gi += 8) {
        float s = 0.f;
#pragma unroll
        for (int l = 0; l < 4; l++) {
            float x = buf[gi * 128 + lane + 32 * l];
            s += x * x;
        }
#pragma unroll
        for (int off = 16; off; off >>= 1)
            s += __shfl_xor_sync(0xffffffffu, s, off);
        if (lane == 0) rnorm[gi] = rsqrtf(s + 1e-6f);
    }
    __syncthreads();

    const float QSCALE = 0.08838834764831845f;
    for (int i = tid; i < KEY_DIM; i += 256) {
        int kh = i >> 7;
        int d  = i & 127;
        size_t o0 = ((size_t)bt * HK + kh) * KD + d;
        qn[o0] = buf[i] * rnorm[kh] * QSCALE;
        kn[o0] = buf[KEY_DIM + i] * rnorm[HK + kh];
    }

    for (int c = tid; c < VALUE_DIM; c += 256) {
        int cc = 2 * KEY_DIM + c;
        float acc = 0.f;
#pragma unroll
        for (int j = 0; j < 4; j++) {
            int ts = t - 3 + j;
            if (ts >= 0)
                acc += convw[cc * 4 + j] * qkvz[((size_t)b * TT + ts) * QKVZ_N + cc];
        }
        vv[(size_t)bt * VALUE_DIM + c] = silu_f(acc);
    }

    if (tid < HV) {
        float bg = ba[(size_t)bt * 64 + tid];
        float a  = ba[(size_t)bt * 64 + 32 + tid] + dtb[tid];
        bb[(size_t)bt * HV + tid] = 1.f / (1.f + __expf(-bg));
        float sp = (a > 20.f) ? a : log1pf(__expf(a));
        gg[(size_t)bt * HV + tid] = -__expf(Alog[tid]) * sp;
    }
}

// ---------------------------------------------------------------------------
// Gated delta-rule scan
// ---------------------------------------------------------------------------
struct ScanBuf {
    ulonglong2 k[8];
    ulonglong2 q[8];
    float v, eg, beta;
};

__device__ __forceinline__ void scan_load(
    ScanBuf& sb, int t, int b, int kh, int h, int kq, int vcol,
    const float* __restrict__ qn, const float* __restrict__ kn,
    const float* __restrict__ vv, const float* __restrict__ gg,
    const float* __restrict__ bb)
{
    int tc = t < TT ? t : TT - 1;
    size_t ik = (((size_t)b * TT + tc) * HK + kh) * (size_t)KD + kq * 32;
    size_t iv = (((size_t)b * TT + tc) * HV + h) * (size_t)VD + vcol;
    const ulonglong2* kp = (const ulonglong2*)(kn + ik);
    const ulonglong2* qp = (const ulonglong2*)(qn + ik);
#pragma unroll
    for (int i = 0; i < 8; i++) { sb.k[i] = kp[i]; sb.q[i] = qp[i]; }
    sb.v = vv[iv];
    size_t ig = ((size_t)b * TT + tc) * HV + h;
    sb.eg = __expf(gg[ig]);
    sb.beta = bb[ig];
}

__device__ __forceinline__ void scan_step(
    ull* __restrict__ S2, const ScanBuf& sb, int t, int b, int h, int kq,
    int vcol, float* __restrict__ oo)
{
    ull eg2 = pack2(sb.eg, sb.eg);
    ull p2a = 0ull, p2b = 0ull;
#pragma unroll
    for (int i = 0; i < 8; i++) {
        S2[2*i]   = fmul2(S2[2*i],   eg2);
        p2a = ffma2(sb.k[i].x, S2[2*i],   p2a);
        S2[2*i+1] = fmul2(S2[2*i+1], eg2);
        p2b = ffma2(sb.k[i].y, S2[2*i+1], p2b);
    }
    float p = (lo2(p2a) + hi2(p2a)) + (lo2(p2b) + hi2(p2b));
    p += __shfl_xor_sync(0xffffffffu, p, 1);
    p += __shfl_xor_sync(0xffffffffu, p, 2);
    float delta = (sb.v - p) * sb.beta;
    ull d2 = pack2(delta, delta);
    ull o2a = 0ull, o2b = 0ull;
#pragma unroll
    for (int i = 0; i < 8; i++) {
        S2[2*i]   = ffma2(sb.k[i].x, d2, S2[2*i]);
        o2a = ffma2(sb.q[i].x, S2[2*i],   o2a);
        S2[2*i+1] = ffma2(sb.k[i].y, d2, S2[2*i+1]);
        o2b = ffma2(sb.q[i].y, S2[2*i+1], o2b);
    }
    float o = (lo2(o2a) + hi2(o2a)) + (lo2(o2b) + hi2(o2b));
    o += __shfl_xor_sync(0xffffffffu, o, 1);
    o += __shfl_xor_sync(0xffffffffu, o, 2);
    if (kq == 0) {
        size_t iv = (((size_t)b * TT + t) * HV + h) * (size_t)VD + vcol;
        oo[iv] = o;
    }
}

__global__ __launch_bounds__(256, 1) void scan_kernel(
    const float* __restrict__ qn, const float* __restrict__ kn,
    const float* __restrict__ vv, const float* __restrict__ gg,
    const float* __restrict__ bb, float* __restrict__ oo)
{
    const int bh2 = blockIdx.x;
    const int b = bh2 >> 6;
    const int rem = bh2 & 63;
    const int h = rem >> 1;
    const int vhalf = rem & 1;
    const int tid = threadIdx.x;
    const int colL = tid >> 2;
    const int kq = tid & 3;
    const int vcol = vhalf * 64 + colL;
    const int kh = h >> 1;

    ull S2[16];
#pragma unroll
    for (int i = 0; i < 16; i++) S2[i] = 0ull;

    ScanBuf bA, bB;
    scan_load(bA, 0, b, kh, h, kq, vcol, qn, kn, vv, gg, bb);

    for (int t = 0; t < TT; t += 2) {
        scan_load(bB, t + 1, b, kh, h, kq, vcol, qn, kn, vv, gg, bb);
        scan_step(S2, bA, t, b, h, kq, vcol, oo);
        scan_load(bA, t + 2, b, kh, h, kq, vcol, qn, kn, vv, gg, bb);
        scan_step(S2, bB, t + 1, b, h, kq, vcol, oo);
    }
}

// ---------------------------------------------------------------------------
// gated rmsnorm -> f16 output for GEMM2's A operand
// ---------------------------------------------------------------------------
__global__ __launch_bounds__(256) void rmsnorm_kernel(
    const float* __restrict__ oo, const float* __restrict__ qkvz,
    const float* __restrict__ nw, __half* __restrict__ xout)
{
    const int bt = blockIdx.x;
    const int warp = threadIdx.x >> 5;
    const int lane = threadIdx.x & 31;

    for (int hh = warp; hh < HV; hh += 8) {
        const size_t base = ((size_t)bt * HV + hh) * (size_t)VD;
        const float* zz = qkvz + (size_t)bt * QKVZ_N + 2 * KEY_DIM + VALUE_DIM
                          + (size_t)hh * VD;
        float xv[4];
        float ss = 0.f;
#pragma unroll
        for (int i = 0; i < 4; i++) {
            int d = lane + 32 * i;
            float z = zz[d];
            float x = oo[base + d] * silu_f(z);
            xv[i] = x;
            ss += x * x;
        }
#pragma unroll
        for (int off = 16; off; off >>= 1)
            ss += __shfl_xor_sync(0xffffffffu, ss, off);
        float r = rsqrtf(ss * (1.f / 128.f) + 1e-6f);
#pragma unroll
        for (int i = 0; i < 4; i++) {
            int d = lane + 32 * i;
            xout[(size_t)bt * VALUE_DIM + hh * VD + d] =
                __float2half(xv[i] * r * (1.f + nw[d]));
        }
    }
}

// ---------------------------------------------------------------------------
// Launch
// ---------------------------------------------------------------------------
extern "C" void kernel_launch(void* const* d_in, const int* in_sizes, int n_in,
                              void* d_out, int out_size)
{
    const float* hs    = (const float*)d_in[0];
    const float* Wqkvz = (const float*)d_in[1];
    const float* Wba   = (const float*)d_in[2];
    const float* convw = (const float*)d_in[3];
    const float* Alog  = (const float*)d_in[4];
    const float* dtb   = (const float*)d_in[5];
    const float* nw    = (const float*)d_in[6];
    const float* Wout  = (const float*)d_in[7];
    float* out = (float*)d_out;

    float *qkvz, *ba, *qn, *kn, *vv, *oo, *gg, *bb;
    __half *ah, *w1h, *w2h, *xh;
    cudaGetSymbolAddress((void**)&qkvz, g_qkvz);
    cudaGetSymbolAddress((void**)&ba,   g_ba);
    cudaGetSymbolAddress((void**)&qn,   g_qn);
    cudaGetSymbolAddress((void**)&kn,   g_kn);
    cudaGetSymbolAddress((void**)&vv,   g_v);
    cudaGetSymbolAddress((void**)&oo,   g_o);
    cudaGetSymbolAddress((void**)&gg,   g_g);
    cudaGetSymbolAddress((void**)&bb,   g_beta);
    cudaGetSymbolAddress((void**)&ah,   g_ah);
    cudaGetSymbolAddress((void**)&w1h,  g_w1h);
    cudaGetSymbolAddress((void**)&w2h,  g_w2h);
    cudaGetSymbolAddress((void**)&xh,   g_xh);

    cudaFuncSetAttribute(h_gemm_kernel,
                         cudaFuncAttributeMaxDynamicSharedMemorySize, GEMM_SMEM);

    // prep: hs -> f16 [M,K]; weights -> transpose f16 [N,K]
    convert_h_kernel<<<(BT * DD / 4 + 255) / 256, 256>>>(hs, ah, BT * DD / 4);
    transpose_h_kernel<<<dim3(QKVZ_N / 32, DD / 32), 256>>>(Wqkvz, w1h, DD, QKVZ_N);
    transpose_h_kernel<<<dim3(DD / 32, VALUE_DIM / 32), 256>>>(Wout, w2h, VALUE_DIM, DD);

    // 1) qkvz = hs @ W_qkvz : [4096,2048]x[2048,12288]
    h_gemm_kernel<<<dim3(QKVZ_N / 128, BT / 128), 256, GEMM_SMEM>>>(
        ah, w1h, qkvz, BT, QKVZ_N, DD);

    // 2) ba = hs @ W_ba
    ba_kernel<<<BT, 256>>>(hs, Wba, ba);

    // 3) conv + silu + l2norm + gating
    conv_gate_kernel<<<BT, 256>>>(qkvz, ba, convw, Alog, dtb, qn, kn, vv, gg, bb);

    // 4) gated delta rule scan
    scan_kernel<<<128, 256>>>(qn, kn, vv, gg, bb, oo);

    // 5) gated rmsnorm -> f16
    rmsnorm_kernel<<<BT, 256>>>(oo, qkvz, nw, xh);

    // 6) out = x @ W_out : [4096,4096]x[4096,2048]
    h_gemm_kernel<<<dim3(DD / 128, BT / 128), 256, GEMM_SMEM>>>(
        xh, w2h, out, BT, DD, VALUE_DIM);
}

// round 8
// speedup vs baseline: 1.2901x; 1.0818x over previous
#include <cuda_runtime.h>
#include <cuda_fp16.h>
#include <math.h>

typedef unsigned long long ull;
typedef unsigned int u32;

// Problem constants
#define BATCH 2
#define TT 2048
#define DD 2048
#define HK 16
#define HV 32
#define KD 128
#define VD 128
#define KEY_DIM 2048
#define VALUE_DIM 4096
#define QKVZ_S 12416            // 12288 qkvz cols + 64 ba cols + 64 pad
#define BT (BATCH*TT)

// ---------------------------------------------------------------------------
// Scratch
// ---------------------------------------------------------------------------
__device__ __half g_qkvzh[(size_t)BT * QKVZ_S];      // 102 MB  GEMM1 out (f16)
__device__ float g_qn  [(size_t)BT * HK * KD];
__device__ float g_kn  [(size_t)BT * HK * KD];
__device__ float g_v   [(size_t)BT * HV * VD];
__device__ float g_o   [(size_t)BT * HV * VD];
__device__ float g_g   [(size_t)BT * HV];
__device__ float g_beta[(size_t)BT * HV];
__device__ __half g_ah [(size_t)BT * DD];            // hs  fp16      [M,K]
__device__ __half g_w1h[(size_t)QKVZ_S * DD];        // [Wqkvz|Wba|0]^T fp16 [N,K]
__device__ __half g_w2h[(size_t)DD * VALUE_DIM];     // W_out^T fp16  [N,K]
__device__ __half g_xh [(size_t)BT * VALUE_DIM];     // rmsnorm out   [M,K]

// ---------------------------------------------------------------------------
// Helpers
// ---------------------------------------------------------------------------
__device__ __forceinline__ float silu_f(float x) {
    return x / (1.f + __expf(-x));
}
__device__ __forceinline__ ull ffma2(ull a, ull b, ull c) {
    ull d; asm("fma.rn.f32x2 %0, %1, %2, %3;" : "=l"(d) : "l"(a), "l"(b), "l"(c));
    return d;
}
__device__ __forceinline__ ull fmul2(ull a, ull b) {
    ull d; asm("mul.rn.f32x2 %0, %1, %2;" : "=l"(d) : "l"(a), "l"(b));
    return d;
}
__device__ __forceinline__ ull pack2(float x, float y) {
    ull r; asm("mov.b64 %0, {%1, %2};" : "=l"(r) : "f"(x), "f"(y));
    return r;
}
__device__ __forceinline__ float lo2(ull a) { return __uint_as_float((u32)(a & 0xffffffffull)); }
__device__ __forceinline__ float hi2(ull a) { return __uint_as_float((u32)(a >> 32)); }

__device__ __forceinline__ u32 cvta_smem(const void* p) {
    u32 a;
    asm("{ .reg .u64 t; cvta.to.shared.u64 t, %1; cvt.u32.u64 %0, t; }"
        : "=r"(a) : "l"(p));
    return a;
}
__device__ __forceinline__ void cp16(u32 dst, const void* src) {
    asm volatile("cp.async.cg.shared.global [%0], [%1], 16;"
                 :: "r"(dst), "l"(src) : "memory");
}
__device__ __forceinline__ void ldsm4(u32& r0, u32& r1, u32& r2, u32& r3, u32 a) {
    asm volatile("ldmatrix.sync.aligned.m8n8.x4.shared.b16 {%0,%1,%2,%3}, [%4];"
                 : "=r"(r0), "=r"(r1), "=r"(r2), "=r"(r3) : "r"(a));
}
__device__ __forceinline__ void stC(float* p, float a, float b) {
    *(float2*)p = make_float2(a, b);
}
__device__ __forceinline__ void stC(__half* p, float a, float b) {
    *(__half2*)p = __floats2half2_rn(a, b);
}

// ---------------------------------------------------------------------------
// fp16 mma.sync GEMM: C[M,N] = A[M,K](f16) * Bt[N,K](f16)^T, f32 accumulate.
// Tile 128x128x32, 256 threads, warp tile 32x64, m16n8k16, ldmatrix,
// 4-stage cp.async, 2 CTAs/SM. Output type templated (f16 or f32).
// ---------------------------------------------------------------------------
#define ROWB 80
#define SB_OFF (128*ROWB)
#define STAGE_BYTES (2*128*ROWB)           // 20480
#define NSTAGES 4
#define GEMM_SMEM (NSTAGES*STAGE_BYTES)    // 81920

__device__ __forceinline__ void gemm_load_stage(
    u32 sb, const __half* __restrict__ Ag, const __half* __restrict__ Bg,
    int K, int kiter, int buf, int tid)
{
    const u32 st = sb + (u32)buf * STAGE_BYTES;
    const int k0 = kiter * 32;
#pragma unroll
    for (int j = 0; j < 2; j++) {
        int c = tid + j * 256;
        int r = c >> 2, cc = c & 3;
        cp16(st + (u32)(r * ROWB + cc * 16), Ag + (size_t)r * K + k0 + cc * 8);
    }
#pragma unroll
    for (int j = 0; j < 2; j++) {
        int c = tid + j * 256;
        int r = c >> 2, cc = c & 3;
        cp16(st + (u32)(SB_OFF + r * ROWB + cc * 16),
             Bg + (size_t)r * K + k0 + cc * 8);
    }
}

template <typename OutT>
__global__ __launch_bounds__(256, 2) void h_gemm_kernel(
    const __half* __restrict__ A, const __half* __restrict__ Bt,
    OutT* __restrict__ C, int M, int N, int K)
{
    extern __shared__ __align__(16) char smem[];
    const u32 sb = cvta_smem(smem);
    const int tid = threadIdx.x;
    const int bx = blockIdx.x;
    const int by = blockIdx.y;
    const int warp = tid >> 5;
    const int lane = tid & 31;
    const int g = lane >> 2;
    const int tg = lane & 3;
    const int warp_m = warp >> 1;
    const int warp_n = warp & 1;
    const int niters = K >> 5;

    const u32 a_base = sb +
        (u32)((warp_m * 32 + (lane & 15)) * ROWB + ((lane >> 4) << 4));
    const u32 b_base = sb + SB_OFF +
        (u32)((warp_n * 64 + (lane & 15)) * ROWB + ((lane >> 4) << 4));

    const __half* Ag = A + (size_t)(by * 128) * K;
    const __half* Bg = Bt + (size_t)(bx * 128) * K;

    float acc[2][8][4];
#pragma unroll
    for (int mt = 0; mt < 2; mt++)
#pragma unroll
        for (int nt = 0; nt < 8; nt++)
#pragma unroll
            for (int r = 0; r < 4; r++) acc[mt][nt][r] = 0.f;

#pragma unroll
    for (int s = 0; s < NSTAGES - 1; s++) {
        gemm_load_stage(sb, Ag, Bg, K, s, s, tid);
        asm volatile("cp.async.commit_group;" ::: "memory");
    }

    int buf = 0;
    for (int i = 0; i < niters; i++) {
        asm volatile("cp.async.wait_group %0;" :: "n"(NSTAGES - 2) : "memory");
        __syncthreads();

        if (i + NSTAGES - 1 < niters) {
            int nb = buf + NSTAGES - 1; if (nb >= NSTAGES) nb -= NSTAGES;
            gemm_load_stage(sb, Ag, Bg, K, i + NSTAGES - 1, nb, tid);
        }
        asm volatile("cp.async.commit_group;" ::: "memory");

        const u32 ab = a_base + (u32)buf * STAGE_BYTES;
        const u32 bb = b_base + (u32)buf * STAGE_BYTES;
#pragma unroll
        for (int ks = 0; ks < 2; ks++) {
            u32 af[2][4];
#pragma unroll
            for (int mt = 0; mt < 2; mt++)
                ldsm4(af[mt][0], af[mt][1], af[mt][2], af[mt][3],
                      ab + (u32)(mt * 16 * ROWB + ks * 32));
            u32 bf[8][2];
#pragma unroll
            for (int p = 0; p < 4; p++) {
                u32 m0, m1, m2, m3;
                ldsm4(m0, m1, m2, m3, bb + (u32)(p * 16 * ROWB + ks * 32));
                bf[2 * p][0] = m0;     bf[2 * p][1] = m2;
                bf[2 * p + 1][0] = m1; bf[2 * p + 1][1] = m3;
            }
#pragma unroll
            for (int mt = 0; mt < 2; mt++)
#pragma unroll
                for (int nt = 0; nt < 8; nt++) {
                    asm volatile(
                        "mma.sync.aligned.m16n8k16.row.col.f32.f16.f16.f32 "
                        "{%0,%1,%2,%3}, {%4,%5,%6,%7}, {%8,%9}, {%0,%1,%2,%3};\n"
                        : "+f"(acc[mt][nt][0]), "+f"(acc[mt][nt][1]),
                          "+f"(acc[mt][nt][2]), "+f"(acc[mt][nt][3])
                        : "r"(af[mt][0]), "r"(af[mt][1]),
                          "r"(af[mt][2]), "r"(af[mt][3]),
                          "r"(bf[nt][0]), "r"(bf[nt][1]));
                }
        }
        buf++; if (buf >= NSTAGES) buf = 0;
    }

#pragma unroll
    for (int mt = 0; mt < 2; mt++) {
        int row = by * 128 + warp_m * 32 + mt * 16 + g;
#pragma unroll
        for (int nt = 0; nt < 8; nt++) {
            int col = bx * 128 + warp_n * 64 + nt * 8 + tg * 2;
            stC(C + (size_t)row * N + col, acc[mt][nt][0], acc[mt][nt][1]);
            stC(C + (size_t)(row + 8) * N + col, acc[mt][nt][2], acc[mt][nt][3]);
        }
    }
}

// ---------------------------------------------------------------------------
// Prep: elementwise f32 -> f16
// ---------------------------------------------------------------------------
__global__ __launch_bounds__(256) void convert_h_kernel(
    const float* __restrict__ in, __half* __restrict__ out, int n4)
{
    int i = blockIdx.x * 256 + threadIdx.x;
    if (i < n4) {
        float4 v = ((const float4*)in)[i];
        ((__half2*)out)[2 * i] = __floats2half2_rn(v.x, v.y);
        ((__half2*)out)[2 * i + 1] = __floats2half2_rn(v.z, v.w);
    }
}

// ---------------------------------------------------------------------------
// Prep: transpose + f16 round. src [R,C] f32 -> dst [C,R] f16
// ---------------------------------------------------------------------------
__global__ __launch_bounds__(256) void transpose_h_kernel(
    const float* __restrict__ src, __half* __restrict__ dst, int R, int C)
{
    __shared__ float t[32][33];
    const int bx = blockIdx.x * 32;  // C offset
    const int by = blockIdx.y * 32;  // R offset
    const int tx = threadIdx.x & 31;
    const int ty = threadIdx.x >> 5;
#pragma unroll
    for (int j = 0; j < 32; j += 8)
        t[ty + j][tx] = src[(size_t)(by + ty + j) * C + bx + tx];
    __syncthreads();
#pragma unroll
    for (int j = 0; j < 32; j += 8)
        dst[(size_t)(bx + ty + j) * R + by + tx] = __float2half(t[tx][ty + j]);
}

// ---------------------------------------------------------------------------
// Prep: W_ba [2048,64] -> w1h rows 12288..12415 (cols 64..127 zero)
// grid (4, 64): blockIdx.x over padded-C (128), blockIdx.y over R (2048)
// ---------------------------------------------------------------------------
__global__ __launch_bounds__(256) void transpose_ba_kernel(
    const float* __restrict__ src, __half* __restrict__ w1h)
{
    __shared__ float t[32][33];
    const int bx = blockIdx.x * 32;  // col offset (0..127)
    const int by = blockIdx.y * 32;  // row offset (0..2047)
    const int tx = threadIdx.x & 31;
    const int ty = threadIdx.x >> 5;
#pragma unroll
    for (int j = 0; j < 32; j += 8) {
        float v = 0.f;
        if (bx + tx < 64) v = src[(size_t)(by + ty + j) * 64 + bx + tx];
        t[ty + j][tx] = v;
    }
    __syncthreads();
#pragma unroll
    for (int j = 0; j < 32; j += 8)
        w1h[(size_t)(12288 + bx + ty + j) * DD + by + tx] =
            __float2half(t[tx][ty + j]);
}

// ---------------------------------------------------------------------------
// conv + silu + l2norm + gating (qkvz is f16, stride QKVZ_S; ba folded in)
// ---------------------------------------------------------------------------
__global__ __launch_bounds__(256) void conv_gate_kernel(
    const __half* __restrict__ qkvz,
    const float* __restrict__ convw, const float* __restrict__ Alog,
    const float* __restrict__ dtb,
    float* __restrict__ qn, float* __restrict__ kn, float* __restrict__ vv,
    float* __restrict__ gg, float* __restrict__ bb)
{
    const int bt = blockIdx.x;
    const int b = bt / TT;
    const int t = bt % TT;
    const int tid = threadIdx.x;
    __shared__ float buf[2 * KEY_DIM];
    __shared__ float rnorm[2 * HK];

    // q,k channels (0..4095), 2 per thread via half2
#pragma unroll
    for (int it = 0; it < 8; it++) {
        int c2 = tid * 2 + it * 512;
        float4 w0 = *(const float4*)(convw + c2 * 4);
        float4 w1 = *(const float4*)(convw + c2 * 4 + 4);
        float wa0[4] = {w0.x, w0.y, w0.z, w0.w};
        float wa1[4] = {w1.x, w1.y, w1.z, w1.w};
        float a0 = 0.f, a1 = 0.f;
#pragma unroll
        for (int j = 0; j < 4; j++) {
            int ts = t - 3 + j;
            if (ts >= 0) {
                __half2 hv = *(const __half2*)(qkvz +
                    ((size_t)b * TT + ts) * QKVZ_S + c2);
                float2 f = __half22float2(hv);
                a0 += wa0[j] * f.x;
                a1 += wa1[j] * f.y;
            }
        }
        buf[c2] = silu_f(a0);
        buf[c2 + 1] = silu_f(a1);
    }
    __syncthreads();

    const int warp = tid >> 5;
    const int lane = tid & 31;
    for (int gi = warp; gi < 32; gi += 8) {
        float s = 0.f;
#pragma unroll
        for (int l = 0; l < 4; l++) {
            float x = buf[gi * 128 + lane + 32 * l];
            s += x * x;
        }
#pragma unroll
        for (int off = 16; off; off >>= 1)
            s += __shfl_xor_sync(0xffffffffu, s, off);
        if (lane == 0) rnorm[gi] = rsqrtf(s + 1e-6f);
    }
    __syncthreads();

    const float QSCALE = 0.08838834764831845f;
    for (int i = tid; i < KEY_DIM; i += 256) {
        int kh = i >> 7;
        int d  = i & 127;
        size_t o0 = ((size_t)bt * HK + kh) * KD + d;
        qn[o0] = buf[i] * rnorm[kh] * QSCALE;
        kn[o0] = buf[KEY_DIM + i] * rnorm[HK + kh];
    }

    // v channels (4096..8191), 2 per thread
#pragma unroll
    for (int it = 0; it < 8; it++) {
        int c2 = 2 * KEY_DIM + tid * 2 + it * 512;
        float4 w0 = *(const float4*)(convw + c2 * 4);
        float4 w1 = *(const float4*)(convw + c2 * 4 + 4);
        float wa0[4] = {w0.x, w0.y, w0.z, w0.w};
        float wa1[4] = {w1.x, w1.y, w1.z, w1.w};
        float a0 = 0.f, a1 = 0.f;
#pragma unroll
        for (int j = 0; j < 4; j++) {
            int ts = t - 3 + j;
            if (ts >= 0) {
                __half2 hv = *(const __half2*)(qkvz +
                    ((size_t)b * TT + ts) * QKVZ_S + c2);
                float2 f = __half22float2(hv);
                a0 += wa0[j] * f.x;
                a1 += wa1[j] * f.y;
            }
        }
        int cv = c2 - 2 * KEY_DIM;
        vv[(size_t)bt * VALUE_DIM + cv] = silu_f(a0);
        vv[(size_t)bt * VALUE_DIM + cv + 1] = silu_f(a1);
    }

    if (tid < HV) {
        float bg = __half2float(qkvz[(size_t)bt * QKVZ_S + 12288 + tid]);
        float a  = __half2float(qkvz[(size_t)bt * QKVZ_S + 12320 + tid]) + dtb[tid];
        bb[(size_t)bt * HV + tid] = 1.f / (1.f + __expf(-bg));
        float sp = (a > 20.f) ? a : log1pf(__expf(a));
        gg[(size_t)bt * HV + tid] = -__expf(Alog[tid]) * sp;
    }
}

// ---------------------------------------------------------------------------
// Gated delta-rule scan
// ---------------------------------------------------------------------------
struct ScanBuf {
    ulonglong2 k[8];
    ulonglong2 q[8];
    float v, eg, beta;
};

__device__ __forceinline__ void scan_load(
    ScanBuf& sb, int t, int b, int kh, int h, int kq, int vcol,
    const float* __restrict__ qn, const float* __restrict__ kn,
    const float* __restrict__ vv, const float* __restrict__ gg,
    const float* __restrict__ bb)
{
    int tc = t < TT ? t : TT - 1;
    size_t ik = (((size_t)b * TT + tc) * HK + kh) * (size_t)KD + kq * 32;
    size_t iv = (((size_t)b * TT + tc) * HV + h) * (size_t)VD + vcol;
    const ulonglong2* kp = (const ulonglong2*)(kn + ik);
    const ulonglong2* qp = (const ulonglong2*)(qn + ik);
#pragma unroll
    for (int i = 0; i < 8; i++) { sb.k[i] = kp[i]; sb.q[i] = qp[i]; }
    sb.v = vv[iv];
    size_t ig = ((size_t)b * TT + tc) * HV + h;
    sb.eg = __expf(gg[ig]);
    sb.beta = bb[ig];
}

__device__ __forceinline__ void scan_step(
    ull* __restrict__ S2, const ScanBuf& sb, int t, int b, int h, int kq,
    int vcol, float* __restrict__ oo)
{
    ull eg2 = pack2(sb.eg, sb.eg);
    ull p2a = 0ull, p2b = 0ull;
#pragma unroll
    for (int i = 0; i < 8; i++) {
        S2[2*i]   = fmul2(S2[2*i],   eg2);
        p2a = ffma2(sb.k[i].x, S2[2*i],   p2a);
        S2[2*i+1] = fmul2(S2[2*i+1], eg2);
        p2b = ffma2(sb.k[i].y, S2[2*i+1], p2b);
    }
    float p = (lo2(p2a) + hi2(p2a)) + (lo2(p2b) + hi2(p2b));
    p += __shfl_xor_sync(0xffffffffu, p, 1);
    p += __shfl_xor_sync(0xffffffffu, p, 2);
    float delta = (sb.v - p) * sb.beta;
    ull d2 = pack2(delta, delta);
    ull o2a = 0ull, o2b = 0ull;
#pragma unroll
    for (int i = 0; i < 8; i++) {
        S2[2*i]   = ffma2(sb.k[i].x, d2, S2[2*i]);
        o2a = ffma2(sb.q[i].x, S2[2*i],   o2a);
        S2[2*i+1] = ffma2(sb.k[i].y, d2, S2[2*i+1]);
        o2b = ffma2(sb.q[i].y, S2[2*i+1], o2b);
    }
    float o = (lo2(o2a) + hi2(o2a)) + (lo2(o2b) + hi2(o2b));
    o += __shfl_xor_sync(0xffffffffu, o, 1);
    o += __shfl_xor_sync(0xffffffffu, o, 2);
    if (kq == 0) {
        size_t iv = (((size_t)b * TT + t) * HV + h) * (size_t)VD + vcol;
        oo[iv] = o;
    }
}

__global__ __launch_bounds__(256, 1) void scan_kernel(
    const float* __restrict__ qn, const float* __restrict__ kn,
    const float* __restrict__ vv, const float* __restrict__ gg,
    const float* __restrict__ bb, float* __restrict__ oo)
{
    const int bh2 = blockIdx.x;
    const int b = bh2 >> 6;
    const int rem = bh2 & 63;
    const int h = rem >> 1;
    const int vhalf = rem & 1;
    const int tid = threadIdx.x;
    const int colL = tid >> 2;
    const int kq = tid & 3;
    const int vcol = vhalf * 64 + colL;
    const int kh = h >> 1;

    ull S2[16];
#pragma unroll
    for (int i = 0; i < 16; i++) S2[i] = 0ull;

    ScanBuf bA, bB;
    scan_load(bA, 0, b, kh, h, kq, vcol, qn, kn, vv, gg, bb);

    for (int t = 0; t < TT; t += 2) {
        scan_load(bB, t + 1, b, kh, h, kq, vcol, qn, kn, vv, gg, bb);
        scan_step(S2, bA, t, b, h, kq, vcol, oo);
        scan_load(bA, t + 2, b, kh, h, kq, vcol, qn, kn, vv, gg, bb);
        scan_step(S2, bB, t + 1, b, h, kq, vcol, oo);
    }
}

// ---------------------------------------------------------------------------
// gated rmsnorm -> f16 output for GEMM2's A operand (z from f16 qkvz)
// ---------------------------------------------------------------------------
__global__ __launch_bounds__(256) void rmsnorm_kernel(
    const float* __restrict__ oo, const __half* __restrict__ qkvz,
    const float* __restrict__ nw, __half* __restrict__ xout)
{
    const int bt = blockIdx.x;
    const int warp = threadIdx.x >> 5;
    const int lane = threadIdx.x & 31;

    for (int hh = warp; hh < HV; hh += 8) {
        const size_t base = ((size_t)bt * HV + hh) * (size_t)VD;
        const __half* zz = qkvz + (size_t)bt * QKVZ_S + 2 * KEY_DIM + VALUE_DIM
                           + (size_t)hh * VD;
        float xv[4];
        float ss = 0.f;
#pragma unroll
        for (int i = 0; i < 4; i++) {
            int d = lane + 32 * i;
            float z = __half2float(zz[d]);
            float x = oo[base + d] * silu_f(z);
            xv[i] = x;
            ss += x * x;
        }
#pragma unroll
        for (int off = 16; off; off >>= 1)
            ss += __shfl_xor_sync(0xffffffffu, ss, off);
        float r = rsqrtf(ss * (1.f / 128.f) + 1e-6f);
#pragma unroll
        for (int i = 0; i < 4; i++) {
            int d = lane + 32 * i;
            xout[(size_t)bt * VALUE_DIM + hh * VD + d] =
                __float2half(xv[i] * r * (1.f + nw[d]));
        }
    }
}

// ---------------------------------------------------------------------------
// Launch
// ---------------------------------------------------------------------------
extern "C" void kernel_launch(void* const* d_in, const int* in_sizes, int n_in,
                              void* d_out, int out_size)
{
    const float* hs    = (const float*)d_in[0];
    const float* Wqkvz = (const float*)d_in[1];
    const float* Wba   = (const float*)d_in[2];
    const float* convw = (const float*)d_in[3];
    const float* Alog  = (const float*)d_in[4];
    const float* dtb   = (const float*)d_in[5];
    const float* nw    = (const float*)d_in[6];
    const float* Wout  = (const float*)d_in[7];
    float* out = (float*)d_out;

    float *qn, *kn, *vv, *oo, *gg, *bb;
    __half *qkvzh, *ah, *w1h, *w2h, *xh;
    cudaGetSymbolAddress((void**)&qkvzh, g_qkvzh);
    cudaGetSymbolAddress((void**)&qn,   g_qn);
    cudaGetSymbolAddress((void**)&kn,   g_kn);
    cudaGetSymbolAddress((void**)&vv,   g_v);
    cudaGetSymbolAddress((void**)&oo,   g_o);
    cudaGetSymbolAddress((void**)&gg,   g_g);
    cudaGetSymbolAddress((void**)&bb,   g_beta);
    cudaGetSymbolAddress((void**)&ah,   g_ah);
    cudaGetSymbolAddress((void**)&w1h,  g_w1h);
    cudaGetSymbolAddress((void**)&w2h,  g_w2h);
    cudaGetSymbolAddress((void**)&xh,   g_xh);

    cudaFuncSetAttribute(h_gemm_kernel<__half>,
                         cudaFuncAttributeMaxDynamicSharedMemorySize, GEMM_SMEM);
    cudaFuncSetAttribute(h_gemm_kernel<float>,
                         cudaFuncAttributeMaxDynamicSharedMemorySize, GEMM_SMEM);

    // prep
    convert_h_kernel<<<(BT * DD / 4 + 255) / 256, 256>>>(hs, ah, BT * DD / 4);
    transpose_h_kernel<<<dim3(12288 / 32, DD / 32), 256>>>(Wqkvz, w1h, DD, 12288);
    transpose_ba_kernel<<<dim3(4, 64), 256>>>(Wba, w1h);
    transpose_h_kernel<<<dim3(DD / 32, VALUE_DIM / 32), 256>>>(Wout, w2h, VALUE_DIM, DD);

    // 1) [qkvz | ba] = hs @ [W_qkvz | W_ba | 0]  : [4096,2048]x[2048,12416]
    h_gemm_kernel<__half><<<dim3(QKVZ_S / 128, BT / 128), 256, GEMM_SMEM>>>(
        ah, w1h, qkvzh, BT, QKVZ_S, DD);

    // 2) conv + silu + l2norm + gating
    conv_gate_kernel<<<BT, 256>>>(qkvzh, convw, Alog, dtb, qn, kn, vv, gg, bb);

    // 3) gated delta rule scan
    scan_kernel<<<128, 256>>>(qn, kn, vv, gg, bb, oo);

    // 4) gated rmsnorm -> f16
    rmsnorm_kernel<<<BT, 256>>>(oo, qkvzh, nw, xh);

    // 5) out = x @ W_out : [4096,4096]x[4096,2048]
    h_gemm_kernel<float><<<dim3(DD / 128, BT / 128), 256, GEMM_SMEM>>>(
        xh, w2h, out, BT, DD, VALUE_DIM);
}